// round 15
// baseline (speedup 1.0000x reference)
#include <cuda_runtime.h>
#include <cuda_bf16.h>
#include <cuda_fp16.h>
#include <math.h>

#define NN 50000
#define NNP 50048
#define EE 800000
#define GG 256
#define LL 1000
#define HH 4
#define CC 32
#define FDIM 78
#define EDIM 128
#define VOC 26
#define KK 8
#define LOUTD 993
#define HC 128
#define XTF (CC*LOUTD)
#define SCAT_BLOCKS ((EE+255)/256)
#define TB_BLOCKS (NNP/128)        // 391
#define XSTR 96
#define WH_PER_LAYER (4*128*32)
#define XH_ELEMS (NNP*XSTR)
#define CB2_BLOCKS ((XTF+255)/256) // 125
#define AGG_BLOCKS ((NN+7)/8)      // 6250
#define SBUF_BYTES 46080

typedef unsigned long long ull;
typedef unsigned int uint32;

__device__ __forceinline__ ull pack2(float x, float y) {
    ull r; asm("mov.b64 %0, {%1, %2};" : "=l"(r) : "f"(x), "f"(y)); return r;
}
__device__ __forceinline__ void fma2(ull& acc, ull a, ull b) {
    asm("fma.rn.f32x2 %0, %1, %2, %0;" : "+l"(acc) : "l"(a), "l"(b));
}
__device__ __forceinline__ float2 unpack2(ull v) {
    float2 f; asm("mov.b64 {%0, %1}, %2;" : "=f"(f.x), "=f"(f.y) : "l"(v)); return f;
}
__device__ __forceinline__ void mma16816(float* c, const uint32* a, uint32 b0, uint32 b1) {
    asm volatile("mma.sync.aligned.m16n8k16.row.col.f32.f16.f16.f32 "
        "{%0,%1,%2,%3}, {%4,%5,%6,%7}, {%8,%9}, {%0,%1,%2,%3};"
        : "+f"(c[0]), "+f"(c[1]), "+f"(c[2]), "+f"(c[3])
        : "r"(a[0]), "r"(a[1]), "r"(a[2]), "r"(a[3]), "r"(b0), "r"(b1));
}
__device__ __forceinline__ void cpasync16(uint32 smem_dst, const void* gsrc) {
    asm volatile("cp.async.cg.shared.global [%0], [%1], 16;\n"
                 :: "r"(smem_dst), "l"(gsrc) : "memory");
}
__device__ __forceinline__ void cpcommit() {
    asm volatile("cp.async.commit_group;\n" ::: "memory");
}
template <int N>
__device__ __forceinline__ void cpwait() {
    asm volatile("cp.async.wait_group %0;\n" :: "n"(N) : "memory");
}

// ---------------- scratch ----------------
__device__ __align__(128) __half g_hh[NN*HC];
__device__ __align__(128) __half g_outh[NNP*HC];
__device__ __align__(128) __half g_xh[XH_ELEMS];
__device__ __align__(128) __half g_Wh[5*WH_PER_LAYER];
__device__ __align__(16)  float g_asrc[NN*4];
__device__ __align__(16)  float g_adst[NN*4];
__device__ int   g_rowptr[NN+1];
__device__ int   g_hcnt[NN];
__device__ int   g_cursor[NN];
__device__ int   g_csr[EE];
__device__ __align__(128) __half g_Bh[VOC*LL*HC];
__device__ float g_wsum[VOC*KK*CC];
__device__ float g_cb2[HC];
__device__ __align__(16) float g_pooled[GG*HC];
__device__ float g_xtpre[GG*HC];
__device__ float g_xc[GG*256];
__device__ float g_h1[GG*1024];
__device__ float g_h2[GG*256];

// ---------------- hist + zero-init ----------------
__global__ void k_hist(const int* __restrict__ dst) {
    int i = blockIdx.x*256 + threadIdx.x;
    if (i < EE) atomicAdd(&g_hcnt[dst[i]], 1);
    if (i < GG*HC) { g_pooled[i] = 0.f; g_xtpre[i] = 0.f; }
    if (i < HC) g_cb2[i] = 0.f;
}

// ---------------- prep + scan (block 0 = scan, 256 threads) ----------------
__device__ void scan_body256() {
    __shared__ int sS[256];
    int t = threadIdx.x;
    const int CH = 196;                  // 256*196 >= 50000
    int b0 = t*CH;
    int sum = 0;
    for (int i = 0; i < CH; i++) { int idx = b0+i; if (idx < NN) sum += g_hcnt[idx]; }
    sS[t] = sum; __syncthreads();
    for (int off = 1; off < 256; off <<= 1) {
        int v = (t >= off) ? sS[t-off] : 0;
        __syncthreads();
        sS[t] += v;
        __syncthreads();
    }
    int run = sS[t] - sum;
    for (int i = 0; i < CH; i++) {
        int idx = b0+i;
        if (idx < NN) {
            int dg = g_hcnt[idx];
            g_rowptr[idx] = run;
            g_cursor[idx] = run;
            g_hcnt[idx] = 0;
            run += dg;
        }
    }
    if (t == 255) g_rowptr[NN] = sS[255];
}

__global__ void k_prep_scan(const float* __restrict__ x, const float* __restrict__ W1,
                            const float* __restrict__ Ws) {
    if (blockIdx.x == 0) { scan_body256(); return; }
    int idx = (blockIdx.x - 1)*256 + threadIdx.x;
    if (idx < XH_ELEMS) {
        int n = idx / XSTR, f = idx - n*XSTR;
        float v = (n < NN && f < FDIM) ? x[n*FDIM + f] : 0.f;
        g_xh[idx] = __float2half_rn(v);
        return;
    }
    int j = idx - XH_ELEMS;
    if (j < 5*WH_PER_LAYER) {
        int l  = j / WH_PER_LAYER;
        int r  = j - l*WH_PER_LAYER;
        int ch = r >> 12;
        int r2 = r & 4095;
        int col = r2 >> 5;
        int kk  = r2 & 31;
        int f = ch*32 + kk;
        int Fin = (l == 0) ? FDIM : HC;
        const float* Wp = (l == 0) ? W1 : (Ws + (l-1)*HC*HC);
        float v = (f < Fin) ? Wp[f*HC + col] : 0.f;
        g_Wh[j] = __float2half_rn(v);
    }
}

// ---------------- scatter + wsum ----------------
__global__ void k_scat_wsum(const int* __restrict__ src, const int* __restrict__ dst,
                            const float* __restrict__ emb, const float* __restrict__ cw) {
    if (blockIdx.x < VOC) {
        int v = blockIdx.x, t = threadIdx.x;
        if (t >= CC*KK) return;
        int o = t >> 3, k = t & 7;
        float acc = 0.f;
        for (int i = 0; i < EDIM; i++) acc += emb[v*EDIM + i]*cw[(o*EDIM + i)*KK + k];
        g_wsum[(v*KK + k)*CC + o] = acc;
        return;
    }
    int i = (blockIdx.x - VOC)*256 + threadIdx.x;
    if (i < EE) {
        int p = atomicAdd(&g_cursor[dst[i]], 1);
        g_csr[p] = src[i];
    }
}

// ---------------- transform body (fp16 act, cp.async, sbuf) ----------------
__device__ __forceinline__ void transform_body5(
        char* sbuf, int n0, const __half* __restrict__ act, int strideHalfs, int nCh,
        const __half* __restrict__ Wh,
        const float* __restrict__ asv, const float* __restrict__ adv) {
    __half* A_s = (__half*)sbuf;
    __half* B_s = (__half*)(sbuf + 20480);
    float* sAs = (float*)(sbuf + 40960);
    float* sAd = (float*)(sbuf + 43008);
    float* sAv = (float*)(sbuf + 45056);
    float* sDv = (float*)(sbuf + 45568);
    int tid = threadIdx.x;
    int warp = tid >> 5, lane = tid & 31;
    int wr = warp & 3, wc = warp >> 2;
    int lr = lane >> 2, hk = lane & 3;

    uint32 sA0 = (uint32)__cvta_generic_to_shared(A_s);
    uint32 sB0 = (uint32)__cvta_generic_to_shared(B_s);
    const int BUFB = 128*40*2;
    size_t strideB = (size_t)strideHalfs*2;
    const char* actB = (const char*)(act) + (size_t)n0*strideB;
    const char* WhB  = (const char*)Wh;

    for (int i = tid; i < 512; i += 256) { sAs[i] = 0.f; sAd[i] = 0.f; }
    if (tid < 128) { sAv[tid] = asv[tid]; sDv[tid] = adv[tid]; }

    int g0i = tid >> 2, g0g = tid & 3;
    int g1i = (tid + 256) >> 2, g1g = (tid + 256) & 3;

    {
        cpasync16(sA0 + g0i*80 + g0g*16, actB + (size_t)g0i*strideB + g0g*16);
        cpasync16(sA0 + g1i*80 + g1g*16, actB + (size_t)g1i*strideB + g1g*16);
        cpasync16(sB0 + g0i*80 + g0g*16, WhB + g0i*64 + g0g*16);
        cpasync16(sB0 + g1i*80 + g1g*16, WhB + g1i*64 + g1g*16);
        cpcommit();
    }

    float c[2][8][4];
#pragma unroll
    for (int mi = 0; mi < 2; mi++)
#pragma unroll
        for (int ni = 0; ni < 8; ni++)
#pragma unroll
            for (int q = 0; q < 4; q++) c[mi][ni][q] = 0.f;

    for (int ci = 0; ci < nCh; ci++) {
        int buf = ci & 1;
        if (ci + 1 < nCh) {
            int nb = buf ^ 1;
            const char* aSrc = actB + (size_t)(ci+1)*64;
            const char* bSrc = WhB + (size_t)(ci+1)*8192;
            cpasync16(sA0 + nb*BUFB + g0i*80 + g0g*16, aSrc + (size_t)g0i*strideB + g0g*16);
            cpasync16(sA0 + nb*BUFB + g1i*80 + g1g*16, aSrc + (size_t)g1i*strideB + g1g*16);
            cpasync16(sB0 + nb*BUFB + g0i*80 + g0g*16, bSrc + g0i*64 + g0g*16);
            cpasync16(sB0 + nb*BUFB + g1i*80 + g1g*16, bSrc + g1i*64 + g1g*16);
            cpcommit();
            cpwait<1>();
        } else {
            cpwait<0>();
        }
        __syncthreads();
        const __half* As = A_s + buf*5120;
        const __half* Bs = B_s + buf*5120;
#pragma unroll
        for (int kk = 0; kk < 32; kk += 16) {
            uint32 a[2][4];
#pragma unroll
            for (int mi = 0; mi < 2; mi++) {
                int r = wr*32 + mi*16 + lr;
                int base = r*40 + kk + 2*hk;
                a[mi][0] = *(const uint32*)&As[base];
                a[mi][1] = *(const uint32*)&As[base + 8*40];
                a[mi][2] = *(const uint32*)&As[base + 8];
                a[mi][3] = *(const uint32*)&As[base + 8*40 + 8];
            }
#pragma unroll
            for (int ni = 0; ni < 8; ni++) {
                int cb = wc*64 + ni*8 + lr;
                int bbase = cb*40 + kk + 2*hk;
                uint32 b0 = *(const uint32*)&Bs[bbase];
                uint32 b1 = *(const uint32*)&Bs[bbase + 8];
                mma16816(c[0][ni], a[0], b0, b1);
                mma16816(c[1][ni], a[1], b0, b1);
            }
        }
        __syncthreads();
    }

    int lc2 = 2*hk;
#pragma unroll
    for (int mi = 0; mi < 2; mi++) {
        int r0l = wr*32 + mi*16 + lr;
        int r1l = r0l + 8;
        float ps[2][2] = {{0.f,0.f},{0.f,0.f}};
        float pd[2][2] = {{0.f,0.f},{0.f,0.f}};
#pragma unroll
        for (int ni = 0; ni < 8; ni++) {
            int colb = wc*64 + ni*8 + lc2;
            int hl = ni >> 2;
            float av0 = sAv[colb], av1 = sAv[colb+1];
            float dv0 = sDv[colb], dv1 = sDv[colb+1];
            float c0 = c[mi][ni][0], c1 = c[mi][ni][1];
            float c2v = c[mi][ni][2], c3v = c[mi][ni][3];
            ps[0][hl] += c0*av0 + c1*av1;  pd[0][hl] += c0*dv0 + c1*dv1;
            ps[1][hl] += c2v*av0 + c3v*av1; pd[1][hl] += c2v*dv0 + c3v*dv1;
            int n0g = n0 + r0l, n1g = n0 + r1l;
            if (n0g < NN) *(__half2*)&g_hh[n0g*HC + colb] = __floats2half2_rn(c0, c1);
            if (n1g < NN) *(__half2*)&g_hh[n1g*HC + colb] = __floats2half2_rn(c2v, c3v);
        }
        int hb = wc*2;
        atomicAdd(&sAs[r0l*4 + hb + 0], ps[0][0]);
        atomicAdd(&sAs[r0l*4 + hb + 1], ps[0][1]);
        atomicAdd(&sAs[r1l*4 + hb + 0], ps[1][0]);
        atomicAdd(&sAs[r1l*4 + hb + 1], ps[1][1]);
        atomicAdd(&sAd[r0l*4 + hb + 0], pd[0][0]);
        atomicAdd(&sAd[r0l*4 + hb + 1], pd[0][1]);
        atomicAdd(&sAd[r1l*4 + hb + 0], pd[1][0]);
        atomicAdd(&sAd[r1l*4 + hb + 1], pd[1][1]);
    }
    __syncthreads();
    for (int i = tid; i < 512; i += 256) {
        int n = n0 + (i >> 2);
        if (n < NN) {
            g_asrc[n*4 + (i & 3)] = sAs[i];
            g_adst[n*4 + (i & 3)] = sAd[i];
        }
    }
}

// ---------------- bbuild body (256 threads, sbuf) ----------------
__device__ __forceinline__ void bbuild_body(char* sbuf, int tau,
                                            const float* __restrict__ Wx) {
    float* ws  = (float*)sbuf;
    float* sWx = (float*)(sbuf + 26624);
    int tid = threadIdx.x;
    int jq = tid & 31;
    int vg = tid >> 5;
    const int vbaseT[8] = {0,4,8,11,14,17,20,23};
    int vbase = vbaseT[vg];
    int vcnt = (vg < 2) ? 4 : 3;
    for (int i = tid; i < VOC*KK*CC; i += 256) ws[i] = g_wsum[i];

    ull acc2[4][2];
#pragma unroll
    for (int vi = 0; vi < 4; vi++) { acc2[vi][0] = 0ULL; acc2[vi][1] = 0ULL; }

    int t0 = tau - 7; if (t0 < 0) t0 = 0;
    int t1 = tau;     if (t1 > LOUTD-1) t1 = LOUTD-1;

    float4 pr[4];
#pragma unroll
    for (int n = 0; n < 4; n++) {
        int i = tid*4 + n*1024;
        pr[n] = *(const float4*)&Wx[((i >> 7)*LOUTD + t0)*HC + (i & 127)];
    }

    for (int t = t0; t <= t1; t++) {
        __syncthreads();
#pragma unroll
        for (int n = 0; n < 4; n++) {
            int i = tid*4 + n*1024;
            *(float4*)&sWx[i] = pr[n];
        }
        __syncthreads();
        if (t < t1) {
#pragma unroll
            for (int n = 0; n < 4; n++) {
                int i = tid*4 + n*1024;
                pr[n] = *(const float4*)&Wx[((i >> 7)*LOUTD + t + 1)*HC + (i & 127)];
            }
        }
        int k = tau - t;
#pragma unroll 4
        for (int o = 0; o < CC; o++) {
            union { float4 v; ull u[2]; } wv;
            wv.v = *(const float4*)&sWx[o*HC + jq*4];
#pragma unroll
            for (int vi = 0; vi < 4; vi++) {
                if (vi < vcnt) {
                    float s = ws[((vbase + vi)*KK + k)*CC + o];
                    ull sd = pack2(s, s);
                    fma2(acc2[vi][0], sd, wv.u[0]);
                    fma2(acc2[vi][1], sd, wv.u[1]);
                }
            }
        }
    }
    for (int vi = 0; vi < vcnt; vi++) {
        float2 p0 = unpack2(acc2[vi][0]);
        float2 p1 = unpack2(acc2[vi][1]);
        union { uint2 u; __half2 h[2]; } o;
        o.h[0] = __floats2half2_rn(p0.x, p0.y);
        o.h[1] = __floats2half2_rn(p1.x, p1.y);
        *(uint2*)&g_Bh[((vbase + vi)*LL + tau)*HC + jq*4] = o.u;
    }
}

// ---------------- fused1: INTERLEAVED transform L1 | bbuild | cb2 -----------
// group g = b>>2, slot s = b&3: s==0 transform[g]; else fb=g*3+s-1:
//   fb<1000 -> bbuild(fb); else cb2(fb-1000)
__global__ void __launch_bounds__(256) k_fused1(
        const float* __restrict__ asv, const float* __restrict__ adv,
        const float* __restrict__ cb, const float* __restrict__ Wx) {
    __shared__ __align__(16) char sbuf[SBUF_BYTES];
    int g = blockIdx.x >> 2, s = blockIdx.x & 3;
    if (s == 0) {
        if (g < TB_BLOCKS) transform_body5(sbuf, g*128, g_xh, XSTR, 3, g_Wh, asv, adv);
        return;
    }
    int fb = g*3 + (s - 1);
    if (fb < LL) { bbuild_body(sbuf, fb, Wx); return; }
    fb -= LL;
    if (fb < CB2_BLOCKS) {
        int j = threadIdx.x & 127, rh = threadIdx.x >> 7;
        int r0 = fb*256 + rh*128;
        float local = 0.f;
        for (int r = r0; r < r0+128 && r < XTF; r++)
            local += cb[r/LOUTD]*Wx[r*HC + j];
        atomicAdd(&g_cb2[j], local);
    }
}

// ---------------- t5a: INTERLEAVED transform L2 | applyB --------------------
__global__ void __launch_bounds__(256) k_t5a(
        const float* __restrict__ asv, const float* __restrict__ adv,
        const int* __restrict__ tgt) {
    __shared__ __align__(16) char sbuf[SBUF_BYTES];
    int g = blockIdx.x >> 2, s = blockIdx.x & 3;
    if (s == 0) {
        if (g < TB_BLOCKS)
            transform_body5(sbuf, g*128, g_outh, HC, 4, g_Wh + WH_PER_LAYER, asv, adv);
        return;
    }
    int ab = g*3 + (s - 1);
    if (ab >= 1024) return;
    int gg = ab >> 2, quarter = ab & 3;
    int j = threadIdx.x & 127, sub = threadIdx.x >> 7;
    int t0 = quarter*250 + sub*125;
    float acc = 0.f;
#pragma unroll 5
    for (int tau = t0; tau < t0+125; tau++) {
        int v = __ldg(&tgt[gg*LL + tau]);
        acc += __half2float(g_Bh[(v*LL + tau)*HC + j]);
    }
    atomicAdd(&g_xtpre[gg*HC + j], acc);
}

// standalone transform (layers 3..5)
__global__ void __launch_bounds__(256) k_transform5(
        int layer, const float* __restrict__ asv, const float* __restrict__ adv) {
    __shared__ __align__(16) char sbuf[SBUF_BYTES];
    transform_body5(sbuf, blockIdx.x*128, g_outh, HC, 4,
                    g_Wh + layer*WH_PER_LAYER, asv, adv);
}

__device__ __forceinline__ float lrelu02(float v) { return v > 0.f ? v : 0.2f*v; }

// ---------------- aggregate (+optional appended xtfin blocks) ---------------
__global__ void k_aggregate(const float* __restrict__ bias, int isLast,
                            const int* __restrict__ batch,
                            const float* __restrict__ xtb) {
    if (blockIdx.x >= AGG_BLOCKS) {
        // xtfin: 128 extra blocks
        int idx = blockIdx.x - AGG_BLOCKS;
        int g = idx*2 + (threadIdx.x >> 7);
        int j = threadIdx.x & 127;
        float v = g_xtpre[g*HC + j] + xtb[j] + g_cb2[j];
        g_xc[g*256 + 128 + j] = v > 0.f ? v : 0.f;
        return;
    }
    __shared__ __align__(16) int   sSrc[8][32];
    __shared__ __align__(16) float sPT[8][4][32];
    int w = threadIdx.x >> 5, lane = threadIdx.x & 31;
    int d = blockIdx.x*8 + w;
    if (d >= NN) return;
    int r0 = g_rowptr[d], r1 = g_rowptr[d+1];
    int M = r1 - r0 + 1;
    float4 adst = *(const float4*)&g_adst[d*4];

    float4 dsum = make_float4(0.f, 0.f, 0.f, 0.f);
    float4 acc  = make_float4(0.f, 0.f, 0.f, 0.f);
    int head = lane >> 3;
    const float* pkRow = &sPT[w][0][0] + head*32;
    const char* hhBase = (const char*)g_hh + 8*lane;
    for (int cb = 0; cb < M; cb += 32) {
        int i = cb + lane;
        float4 p = make_float4(0.f, 0.f, 0.f, 0.f);
        int s = 0;
        if (i < M) {
            s = (i == 0) ? d : g_csr[r0 + i - 1];
            float4 a = *(const float4*)&g_asrc[s*4];
            p.x = __expf(lrelu02(a.x + adst.x));
            p.y = __expf(lrelu02(a.y + adst.y));
            p.z = __expf(lrelu02(a.z + adst.z));
            p.w = __expf(lrelu02(a.w + adst.w));
            dsum.x += p.x; dsum.y += p.y; dsum.z += p.z; dsum.w += p.w;
        }
        sSrc[w][lane] = s;
        sPT[w][0][lane] = p.x; sPT[w][1][lane] = p.y;
        sPT[w][2][lane] = p.z; sPT[w][3][lane] = p.w;
        __syncwarp();
        int cnt = M - cb; if (cnt > 32) cnt = 32;
        int j = 0;
        for (; j + 4 <= cnt; j += 4) {
            int4  s4  = *(const int4*)&sSrc[w][j];
            float4 pk = *(const float4*)&pkRow[j];
            uint2 h0 = *(const uint2*)(hhBase + (size_t)s4.x*256);
            uint2 h1 = *(const uint2*)(hhBase + (size_t)s4.y*256);
            uint2 h2 = *(const uint2*)(hhBase + (size_t)s4.z*256);
            uint2 h3 = *(const uint2*)(hhBase + (size_t)s4.w*256);
            float2 a0 = __half22float2(*reinterpret_cast<__half2*>(&h0.x));
            float2 b0 = __half22float2(*reinterpret_cast<__half2*>(&h0.y));
            float2 a1 = __half22float2(*reinterpret_cast<__half2*>(&h1.x));
            float2 b1 = __half22float2(*reinterpret_cast<__half2*>(&h1.y));
            float2 a2 = __half22float2(*reinterpret_cast<__half2*>(&h2.x));
            float2 b2 = __half22float2(*reinterpret_cast<__half2*>(&h2.y));
            float2 a3 = __half22float2(*reinterpret_cast<__half2*>(&h3.x));
            float2 b3 = __half22float2(*reinterpret_cast<__half2*>(&h3.y));
            acc.x += pk.x*a0.x + pk.y*a1.x + pk.z*a2.x + pk.w*a3.x;
            acc.y += pk.x*a0.y + pk.y*a1.y + pk.z*a2.y + pk.w*a3.y;
            acc.z += pk.x*b0.x + pk.y*b1.x + pk.z*b2.x + pk.w*b3.x;
            acc.w += pk.x*b0.y + pk.y*b1.y + pk.z*b2.y + pk.w*b3.y;
        }
        for (; j < cnt; j++) {
            int sj = sSrc[w][j];
            float pk = pkRow[j];
            uint2 hv = *(const uint2*)(hhBase + (size_t)sj*256);
            float2 f01 = __half22float2(*reinterpret_cast<__half2*>(&hv.x));
            float2 f23 = __half22float2(*reinterpret_cast<__half2*>(&hv.y));
            acc.x += pk*f01.x; acc.y += pk*f01.y;
            acc.z += pk*f23.x; acc.w += pk*f23.y;
        }
        __syncwarp();
    }
#pragma unroll
    for (int off = 16; off > 0; off >>= 1) {
        dsum.x += __shfl_xor_sync(0xffffffffu, dsum.x, off);
        dsum.y += __shfl_xor_sync(0xffffffffu, dsum.y, off);
        dsum.z += __shfl_xor_sync(0xffffffffu, dsum.z, off);
        dsum.w += __shfl_xor_sync(0xffffffffu, dsum.w, off);
    }
    float den = ((head == 0) ? dsum.x : (head == 1) ? dsum.y : (head == 2) ? dsum.z : dsum.w) + 1e-16f;
    float inv = 1.f/den;
    float4 bv = *(const float4*)&bias[4*lane];
    float4 o;
    o.x = fmaxf(acc.x*inv + bv.x, 0.f);
    o.y = fmaxf(acc.y*inv + bv.y, 0.f);
    o.z = fmaxf(acc.z*inv + bv.z, 0.f);
    o.w = fmaxf(acc.w*inv + bv.w, 0.f);
    if (isLast) {
        float* pp = &g_pooled[batch[d]*HC + 4*lane];
        atomicAdd(pp+0, o.x); atomicAdd(pp+1, o.y);
        atomicAdd(pp+2, o.z); atomicAdd(pp+3, o.w);
    } else {
        union { uint2 u; __half2 h[2]; } oo;
        oo.h[0] = __floats2half2_rn(o.x, o.y);
        oo.h[1] = __floats2half2_rn(o.z, o.w);
        *(uint2*)&g_outh[d*HC + 4*lane] = oo.u;
    }
}

// ---------------- small dense layers ----------------
__global__ void __launch_bounds__(128) k_fc2(int Asel, int lda,
                     const float* __restrict__ W, const float* __restrict__ b,
                     int Csel, int ldc, int K, int Nout, int doRelu) {
    __shared__ float sA[8*1024];
    const float* A = (Asel == 0) ? g_pooled : (Asel == 1) ? g_xc : g_h1;
    float* C = (Csel == 0) ? g_xc : (Csel == 1) ? g_h1 : g_h2;
    int g0 = blockIdx.x*8;
    for (int i = threadIdx.x; i < 8*K; i += 128) {
        int g8 = i / K, k = i - g8*K;
        sA[g8*K + k] = A[(g0+g8)*lda + k];
    }
    __syncthreads();
    int n = blockIdx.y*128 + threadIdx.x;
    if (n >= Nout) return;
    float acc[8];
#pragma unroll
    for (int g8 = 0; g8 < 8; g8++) acc[g8] = 0.f;
#pragma unroll 2
    for (int k = 0; k < K; k++) {
        float w = W[k*Nout + n];
#pragma unroll
        for (int g8 = 0; g8 < 8; g8++) acc[g8] += sA[g8*K + k]*w;
    }
    float bv = b[n];
#pragma unroll
    for (int g8 = 0; g8 < 8; g8++) {
        float v = acc[g8] + bv;
        if (doRelu && v < 0.f) v = 0.f;
        C[(g0+g8)*ldc + n] = v;
    }
}

__global__ void k_out(const float* __restrict__ ow, const float* __restrict__ ob,
                      float* __restrict__ outp) {
    int g = blockIdx.x, lane = threadIdx.x;
    float s = 0.f;
    for (int k = lane; k < 256; k += 32) s += g_h2[g*256 + k]*ow[k];
#pragma unroll
    for (int off = 16; off > 0; off >>= 1) s += __shfl_xor_sync(0xffffffffu, s, off);
    if (lane == 0) outp[g] = s + ob[0];
}

// ---------------- host (single stream) ----------------
extern "C" void kernel_launch(void* const* d_in, const int* in_sizes, int n_in,
                              void* d_out, int out_size) {
    (void)in_sizes; (void)n_in; (void)out_size;
    const float* x       = (const float*)d_in[0];
    const int*   ei      = (const int*)  d_in[1];
    const int*   batch   = (const int*)  d_in[2];
    const int*   target  = (const int*)  d_in[3];
    const float* W1      = (const float*)d_in[4];
    const float* as1     = (const float*)d_in[5];
    const float* ad1     = (const float*)d_in[6];
    const float* b1      = (const float*)d_in[7];
    const float* Ws      = (const float*)d_in[8];
    const float* ass     = (const float*)d_in[9];
    const float* ads     = (const float*)d_in[10];
    const float* bs      = (const float*)d_in[11];
    const float* fcxd_w  = (const float*)d_in[12];
    const float* fcxd_b  = (const float*)d_in[13];
    const float* emb     = (const float*)d_in[14];
    const float* conv_w  = (const float*)d_in[15];
    const float* conv_b  = (const float*)d_in[16];
    const float* fcxt_w  = (const float*)d_in[17];
    const float* fcxt_b  = (const float*)d_in[18];
    const float* fc1_w   = (const float*)d_in[19];
    const float* fc1_b   = (const float*)d_in[20];
    const float* fc2_w   = (const float*)d_in[21];
    const float* fc2_b   = (const float*)d_in[22];
    const float* out_w   = (const float*)d_in[23];
    const float* out_b   = (const float*)d_in[24];
    const int* esrc = ei;
    const int* edst = ei + EE;

    k_hist<<<(EE+255)/256, 256>>>(edst);                                  // 0
    k_prep_scan<<<1 + (XH_ELEMS + 5*WH_PER_LAYER + 255)/256, 256>>>(x, W1, Ws); // 1
    k_scat_wsum<<<VOC + SCAT_BLOCKS, 256>>>(esrc, edst, emb, conv_w);     // 2
    k_fused1<<<4*TB_BLOCKS, 256>>>(as1, ad1, conv_b, fcxt_w);             // 3 (profiled)
    k_aggregate<<<AGG_BLOCKS, 256>>>(b1, 0, batch, nullptr);              // 4

    k_t5a<<<4*TB_BLOCKS, 256>>>(ass + 0*HH*CC, ads + 0*HH*CC, target);    // 5 (L2 | applyB)
    k_aggregate<<<AGG_BLOCKS + 128, 256>>>(bs + 0*HC, 0, batch, fcxt_b);  // 6 (+xtfin)

    k_transform5<<<TB_BLOCKS, 256>>>(2, ass + 1*HH*CC, ads + 1*HH*CC);    // 7
    k_aggregate<<<AGG_BLOCKS, 256>>>(bs + 1*HC, 0, batch, nullptr);       // 8
    k_transform5<<<TB_BLOCKS, 256>>>(3, ass + 2*HH*CC, ads + 2*HH*CC);    // 9
    k_aggregate<<<AGG_BLOCKS, 256>>>(bs + 2*HC, 0, batch, nullptr);       // 10
    k_transform5<<<TB_BLOCKS, 256>>>(4, ass + 3*HH*CC, ads + 3*HH*CC);    // 11
    k_aggregate<<<AGG_BLOCKS, 256>>>(bs + 3*HC, 1, batch, nullptr);       // 12

    k_fc2<<<dim3(GG/8,1), 128>>>(0, HC, fcxd_w, fcxd_b, 0, 256, HC, HC, 1);
    k_fc2<<<dim3(GG/8,8), 128>>>(1, 256,  fc1_w, fc1_b, 1, 1024, 256,  1024, 1);
    k_fc2<<<dim3(GG/8,2), 128>>>(2, 1024, fc2_w, fc2_b, 2, 256,  1024, 256,  1);
    k_out<<<GG, 32>>>(out_w, out_b, (float*)d_out);
}

// round 16
// speedup vs baseline: 1.1307x; 1.1307x over previous
#include <cuda_runtime.h>
#include <cuda_bf16.h>
#include <cuda_fp16.h>
#include <math.h>

#define NN 50000
#define NNP 50048
#define EE 800000
#define GG 256
#define LL 1000
#define HH 4
#define CC 32
#define FDIM 78
#define EDIM 128
#define VOC 26
#define KK 8
#define LOUTD 993
#define HC 128
#define XTF (CC*LOUTD)
#define SCAT_BLOCKS ((EE+255)/256)
#define XSTR 96
#define WH_PER_LAYER (4*128*32)
#define XH_ELEMS (NNP*XSTR)
#define WXH2_ELEMS (LOUTD*32*128)

typedef unsigned long long ull;
typedef unsigned int uint32;

__device__ __forceinline__ void mma16816(float* c, const uint32* a, uint32 b0, uint32 b1) {
    asm volatile("mma.sync.aligned.m16n8k16.row.col.f32.f16.f16.f32 "
        "{%0,%1,%2,%3}, {%4,%5,%6,%7}, {%8,%9}, {%0,%1,%2,%3};"
        : "+f"(c[0]), "+f"(c[1]), "+f"(c[2]), "+f"(c[3])
        : "r"(a[0]), "r"(a[1]), "r"(a[2]), "r"(a[3]), "r"(b0), "r"(b1));
}
__device__ __forceinline__ void ldsm4t(uint32* d, uint32 addr) {
    asm volatile("ldmatrix.sync.aligned.m8n8.x4.trans.shared.b16 {%0,%1,%2,%3}, [%4];"
        : "=r"(d[0]), "=r"(d[1]), "=r"(d[2]), "=r"(d[3]) : "r"(addr));
}
__device__ __forceinline__ void cpasync16(uint32 smem_dst, const void* gsrc) {
    asm volatile("cp.async.cg.shared.global [%0], [%1], 16;\n"
                 :: "r"(smem_dst), "l"(gsrc) : "memory");
}
__device__ __forceinline__ void cpcommit() {
    asm volatile("cp.async.commit_group;\n" ::: "memory");
}
template <int N>
__device__ __forceinline__ void cpwait() {
    asm volatile("cp.async.wait_group %0;\n" :: "n"(N) : "memory");
}

// ---------------- scratch ----------------
__device__ __align__(128) __half g_hh[NN*HC];
__device__ __align__(128) __half g_outh[NNP*HC];
__device__ __align__(128) __half g_xh[XH_ELEMS];
__device__ __align__(128) __half g_Wh[5*WH_PER_LAYER];
__device__ __align__(128) __half g_Wxh2[WXH2_ELEMS];   // [t][o][j] fp16 fcxt_w
__device__ __align__(16)  float g_asrc[NN*4];
__device__ __align__(16)  float g_adst[NN*4];
__device__ int   g_rowptr[NN+1];
__device__ int   g_hcnt[NN];
__device__ int   g_cursor[NN];
__device__ int   g_csr[EE];
__device__ __align__(128) __half g_Bh[VOC*LL*HC];
__device__ float g_wsum[VOC*KK*CC];
__device__ float g_cb2[HC];
__device__ __align__(16) float g_pooled[GG*HC];
__device__ float g_xtpre[GG*HC];
__device__ float g_xc[GG*256];
__device__ float g_h1[GG*1024];
__device__ float g_h2[GG*256];

// ---------------- prep: wsum | x->fp16 | W->fp16 | Wx->fp16 [t][o][j] ------
__global__ void k_prep(const float* __restrict__ x, const float* __restrict__ W1,
                       const float* __restrict__ Ws,
                       const float* __restrict__ emb, const float* __restrict__ cw,
                       const float* __restrict__ Wx) {
    if (blockIdx.x < VOC) {
        int v = blockIdx.x, t = threadIdx.x;
        if (t >= CC*KK) return;
        int o = t >> 3, k = t & 7;
        float acc = 0.f;
        for (int i = 0; i < EDIM; i++) acc += emb[v*EDIM + i]*cw[(o*EDIM + i)*KK + k];
        g_wsum[(v*KK + k)*CC + o] = acc;
        return;
    }
    int idx = (blockIdx.x - VOC)*256 + threadIdx.x;
    if (idx < XH_ELEMS) {
        int n = idx / XSTR, f = idx - n*XSTR;
        float v = (n < NN && f < FDIM) ? x[n*FDIM + f] : 0.f;
        g_xh[idx] = __float2half_rn(v);
        return;
    }
    int j = idx - XH_ELEMS;
    if (j < 5*WH_PER_LAYER) {
        int l  = j / WH_PER_LAYER;
        int r  = j - l*WH_PER_LAYER;
        int ch = r >> 12;
        int r2 = r & 4095;
        int col = r2 >> 5;
        int kk  = r2 & 31;
        int f = ch*32 + kk;
        int Fin = (l == 0) ? FDIM : HC;
        const float* Wp = (l == 0) ? W1 : (Ws + (l-1)*HC*HC);
        float v = (f < Fin) ? Wp[f*HC + col] : 0.f;
        g_Wh[j] = __float2half_rn(v);
        return;
    }
    int m = j - 5*WH_PER_LAYER;
    if (m < WXH2_ELEMS) {
        int t = m >> 12;           // /(32*128)
        int r = m & 4095;
        int o = r >> 7, jj = r & 127;
        g_Wxh2[m] = __float2half_rn(Wx[(o*LOUTD + t)*HC + jj]);
    }
}

// ---------------- CSR build ----------------
__global__ void k_hist(const int* __restrict__ dst) {
    int i = blockIdx.x*256 + threadIdx.x;
    if (i < EE) atomicAdd(&g_hcnt[dst[i]], 1);
}

__global__ void k_scan() {
    __shared__ int sS[1024];
    int t = threadIdx.x;
    const int CH = 49;
    int b0 = t*CH;
    int sum = 0;
    for (int i = 0; i < CH; i++) { int idx = b0+i; if (idx < NN) sum += g_hcnt[idx]; }
    sS[t] = sum; __syncthreads();
    for (int off = 1; off < 1024; off <<= 1) {
        int v = (t >= off) ? sS[t-off] : 0;
        __syncthreads();
        sS[t] += v;
        __syncthreads();
    }
    int run = sS[t] - sum;
    for (int i = 0; i < CH; i++) {
        int idx = b0+i;
        if (idx < NN) {
            int dg = g_hcnt[idx];
            g_rowptr[idx] = run;
            g_cursor[idx] = run;
            g_hcnt[idx] = 0;
            run += dg;
        }
    }
    if (t == 1023) g_rowptr[NN] = sS[1023];
}

// ---------------- bbuild v5: tensor-core MMA ----------------
// Per block tau: B[v, tau, j] = sum_t S_t[o][j] * wsum[v][tau-t][o]
// A = S_t via ldmatrix.x4.trans (smem row-major [o][j], stride 136 halves)
// B = wsum fp16 [k][v(32, stride 40)][o]; D[j][v] fp32 accum.
__global__ void __launch_bounds__(256) k_bbuild5() {
    __shared__ __half wsh[KK*32*40];       // 20480B
    __shared__ __half S_s[2][32*136];      // 2*8704B
    int tau = blockIdx.x;
    int tid = threadIdx.x;
    int warp = tid >> 5, lane = tid & 31;
    int lr = lane >> 2, hk = lane & 3;
    int quad = lane >> 3, qr = lane & 7;

    // zero wsh then fill (v=26..31 stay zero)
    for (int i = tid; i < KK*32*40; i += 256) wsh[i] = __float2half_rn(0.f);
    __syncthreads();
    for (int i = tid; i < VOC*KK*CC; i += 256) {
        int v = i >> 8;              // /(KK*CC)
        int rem = i & 255;
        int k = rem >> 5, o = rem & 31;
        wsh[k*1280 + v*40 + o] = __float2half_rn(g_wsum[i]);
    }

    int t0 = tau - (KK-1); if (t0 < 0) t0 = 0;
    int t1 = tau;          if (t1 > LOUTD-1) t1 = LOUTD-1;

    uint32 sS0 = (uint32)__cvta_generic_to_shared(&S_s[0][0]);
    const char* WB = (const char*)g_Wxh2;

    // prologue: stage slab t0 into buf 0 (512 granules of 16B)
    {
        int g0 = tid, g1 = tid + 256;
        cpasync16(sS0 + (g0 >> 4)*272 + (g0 & 15)*16,
                  WB + (size_t)t0*8192 + (g0 >> 4)*256 + (g0 & 15)*16);
        cpasync16(sS0 + (g1 >> 4)*272 + (g1 & 15)*16,
                  WB + (size_t)t0*8192 + (g1 >> 4)*256 + (g1 & 15)*16);
        cpcommit();
    }
    __syncthreads();   // wsh ready

    float c[4][4];
#pragma unroll
    for (int nt = 0; nt < 4; nt++)
#pragma unroll
        for (int q = 0; q < 4; q++) c[nt][q] = 0.f;

    for (int t = t0; t <= t1; t++) {
        int buf = (t - t0) & 1;
        if (t < t1) {
            int nb = buf ^ 1;
            int g0 = tid, g1 = tid + 256;
            cpasync16(sS0 + nb*8704 + (g0 >> 4)*272 + (g0 & 15)*16,
                      WB + (size_t)(t+1)*8192 + (g0 >> 4)*256 + (g0 & 15)*16);
            cpasync16(sS0 + nb*8704 + (g1 >> 4)*272 + (g1 & 15)*16,
                      WB + (size_t)(t+1)*8192 + (g1 >> 4)*256 + (g1 & 15)*16);
            cpcommit();
            cpwait<1>();
        } else {
            cpwait<0>();
        }
        __syncthreads();
        int k = tau - t;
        uint32 Sb = sS0 + buf*8704;
        const __half* wk = &wsh[k*1280];
#pragma unroll
        for (int kk = 0; kk < 32; kk += 16) {
            uint32 a[4];
            int rowk = kk + ((quad & 2) ? 8 : 0) + qr;
            int colj = warp*16 + ((quad & 1) ? 8 : 0);
            ldsm4t(a, Sb + rowk*272 + colj*2);
#pragma unroll
            for (int nt = 0; nt < 4; nt++) {
                uint32 b0 = *(const uint32*)&wk[(nt*8 + lr)*40 + kk + 2*hk];
                uint32 b1 = *(const uint32*)&wk[(nt*8 + lr)*40 + kk + 2*hk + 8];
                mma16816(c[nt], a, b0, b1);
            }
        }
        __syncthreads();
    }

    // epilogue: D[j][v] -> g_Bh[(v*LL+tau)*HC + j]
    int j0 = warp*16 + lr;
#pragma unroll
    for (int nt = 0; nt < 4; nt++) {
        int v0 = nt*8 + 2*hk, v1 = v0 + 1;
        if (v0 < VOC) {
            g_Bh[((size_t)v0*LL + tau)*HC + j0]     = __float2half_rn(c[nt][0]);
            g_Bh[((size_t)v0*LL + tau)*HC + j0 + 8] = __float2half_rn(c[nt][2]);
        }
        if (v1 < VOC) {
            g_Bh[((size_t)v1*LL + tau)*HC + j0]     = __float2half_rn(c[nt][1]);
            g_Bh[((size_t)v1*LL + tau)*HC + j0 + 8] = __float2half_rn(c[nt][3]);
        }
    }
}

// ---------------- transform body (fp16 act, cp.async) ----------------
__device__ __forceinline__ void transform_body5(
        int n0, const __half* __restrict__ act, int strideHalfs, int nCh,
        const __half* __restrict__ Wh,
        const float* __restrict__ asv, const float* __restrict__ adv) {
    __shared__ __half A_s[2][128*40];
    __shared__ __half B_s[2][128*40];
    __shared__ float sAs[512], sAd[512];
    __shared__ float sAv[128], sDv[128];
    int tid = threadIdx.x;
    int warp = tid >> 5, lane = tid & 31;
    int wr = warp & 3, wc = warp >> 2;
    int lr = lane >> 2, hk = lane & 3;

    uint32 sA0 = (uint32)__cvta_generic_to_shared(&A_s[0][0]);
    uint32 sB0 = (uint32)__cvta_generic_to_shared(&B_s[0][0]);
    const int BUFB = 128*40*2;
    size_t strideB = (size_t)strideHalfs*2;
    const char* actB = (const char*)(act) + (size_t)n0*strideB;
    const char* WhB  = (const char*)Wh;

    for (int i = tid; i < 512; i += 256) { sAs[i] = 0.f; sAd[i] = 0.f; }
    if (tid < 128) { sAv[tid] = asv[tid]; sDv[tid] = adv[tid]; }

    int g0i = tid >> 2, g0g = tid & 3;
    int g1i = (tid + 256) >> 2, g1g = (tid + 256) & 3;

    {
        cpasync16(sA0 + g0i*80 + g0g*16, actB + (size_t)g0i*strideB + g0g*16);
        cpasync16(sA0 + g1i*80 + g1g*16, actB + (size_t)g1i*strideB + g1g*16);
        cpasync16(sB0 + g0i*80 + g0g*16, WhB + g0i*64 + g0g*16);
        cpasync16(sB0 + g1i*80 + g1g*16, WhB + g1i*64 + g1g*16);
        cpcommit();
    }

    float c[2][8][4];
#pragma unroll
    for (int mi = 0; mi < 2; mi++)
#pragma unroll
        for (int ni = 0; ni < 8; ni++)
#pragma unroll
            for (int q = 0; q < 4; q++) c[mi][ni][q] = 0.f;

    for (int ci = 0; ci < nCh; ci++) {
        int buf = ci & 1;
        if (ci + 1 < nCh) {
            int nb = buf ^ 1;
            const char* aSrc = actB + (size_t)(ci+1)*64;
            const char* bSrc = WhB + (size_t)(ci+1)*8192;
            cpasync16(sA0 + nb*BUFB + g0i*80 + g0g*16, aSrc + (size_t)g0i*strideB + g0g*16);
            cpasync16(sA0 + nb*BUFB + g1i*80 + g1g*16, aSrc + (size_t)g1i*strideB + g1g*16);
            cpasync16(sB0 + nb*BUFB + g0i*80 + g0g*16, bSrc + g0i*64 + g0g*16);
            cpasync16(sB0 + nb*BUFB + g1i*80 + g1g*16, bSrc + g1i*64 + g1g*16);
            cpcommit();
            cpwait<1>();
        } else {
            cpwait<0>();
        }
        __syncthreads();
        const __half* As = A_s[buf];
        const __half* Bs = B_s[buf];
#pragma unroll
        for (int kk = 0; kk < 32; kk += 16) {
            uint32 a[2][4];
#pragma unroll
            for (int mi = 0; mi < 2; mi++) {
                int r = wr*32 + mi*16 + lr;
                int base = r*40 + kk + 2*hk;
                a[mi][0] = *(const uint32*)&As[base];
                a[mi][1] = *(const uint32*)&As[base + 8*40];
                a[mi][2] = *(const uint32*)&As[base + 8];
                a[mi][3] = *(const uint32*)&As[base + 8*40 + 8];
            }
#pragma unroll
            for (int ni = 0; ni < 8; ni++) {
                int cb = wc*64 + ni*8 + lr;
                int bbase = cb*40 + kk + 2*hk;
                uint32 b0 = *(const uint32*)&Bs[bbase];
                uint32 b1 = *(const uint32*)&Bs[bbase + 8];
                mma16816(c[0][ni], a[0], b0, b1);
                mma16816(c[1][ni], a[1], b0, b1);
            }
        }
        __syncthreads();
    }

    int lc2 = 2*hk;
#pragma unroll
    for (int mi = 0; mi < 2; mi++) {
        int r0l = wr*32 + mi*16 + lr;
        int r1l = r0l + 8;
        float ps[2][2] = {{0.f,0.f},{0.f,0.f}};
        float pd[2][2] = {{0.f,0.f},{0.f,0.f}};
#pragma unroll
        for (int ni = 0; ni < 8; ni++) {
            int colb = wc*64 + ni*8 + lc2;
            int hl = ni >> 2;
            float av0 = sAv[colb], av1 = sAv[colb+1];
            float dv0 = sDv[colb], dv1 = sDv[colb+1];
            float c0 = c[mi][ni][0], c1 = c[mi][ni][1];
            float c2v = c[mi][ni][2], c3v = c[mi][ni][3];
            ps[0][hl] += c0*av0 + c1*av1;  pd[0][hl] += c0*dv0 + c1*dv1;
            ps[1][hl] += c2v*av0 + c3v*av1; pd[1][hl] += c2v*dv0 + c3v*dv1;
            int n0g = n0 + r0l, n1g = n0 + r1l;
            if (n0g < NN) *(__half2*)&g_hh[n0g*HC + colb] = __floats2half2_rn(c0, c1);
            if (n1g < NN) *(__half2*)&g_hh[n1g*HC + colb] = __floats2half2_rn(c2v, c3v);
        }
        int hb = wc*2;
        atomicAdd(&sAs[r0l*4 + hb + 0], ps[0][0]);
        atomicAdd(&sAs[r0l*4 + hb + 1], ps[0][1]);
        atomicAdd(&sAs[r1l*4 + hb + 0], ps[1][0]);
        atomicAdd(&sAs[r1l*4 + hb + 1], ps[1][1]);
        atomicAdd(&sAd[r0l*4 + hb + 0], pd[0][0]);
        atomicAdd(&sAd[r0l*4 + hb + 1], pd[0][1]);
        atomicAdd(&sAd[r1l*4 + hb + 0], pd[1][0]);
        atomicAdd(&sAd[r1l*4 + hb + 1], pd[1][1]);
    }
    __syncthreads();
    for (int i = tid; i < 512; i += 256) {
        int n = n0 + (i >> 2);
        if (n < NN) {
            g_asrc[n*4 + (i & 3)] = sAs[i];
            g_adst[n*4 + (i & 3)] = sAd[i];
        }
    }
}

__global__ void __launch_bounds__(256) k_transform5(
        int layer, const float* __restrict__ asv, const float* __restrict__ adv) {
    transform_body5(blockIdx.x*128, g_outh, HC, 4,
                    g_Wh + layer*WH_PER_LAYER, asv, adv);
}

__global__ void __launch_bounds__(256) k_scat_transform(
        const int* __restrict__ src, const int* __restrict__ dst,
        const float* __restrict__ asv, const float* __restrict__ adv) {
    if (blockIdx.x < SCAT_BLOCKS) {
        int i = blockIdx.x*256 + threadIdx.x;
        if (i < EE) {
            int p = atomicAdd(&g_cursor[dst[i]], 1);
            g_csr[p] = src[i];
        }
        if (i < GG*HC) { g_pooled[i] = 0.f; g_xtpre[i] = 0.f; }
        if (i < HC) g_cb2[i] = 0.f;
        return;
    }
    transform_body5((blockIdx.x - SCAT_BLOCKS)*128, g_xh, XSTR, 3, g_Wh, asv, adv);
}

__device__ __forceinline__ float lrelu02(float v) { return v > 0.f ? v : 0.2f*v; }

// ---------------- single-pass softmax + aggregate (fp16 gather) -------------
__global__ void k_aggregate(const float* __restrict__ bias, int isLast,
                            const int* __restrict__ batch) {
    __shared__ int    sSrc[8][32];
    __shared__ float4 sP[8][32];
    int w = threadIdx.x >> 5, lane = threadIdx.x & 31;
    int d = blockIdx.x*8 + w;
    if (d >= NN) return;
    int r0 = g_rowptr[d], r1 = g_rowptr[d+1];
    int M = r1 - r0 + 1;
    float4 adst = *(const float4*)&g_adst[d*4];

    float4 dsum = make_float4(0.f, 0.f, 0.f, 0.f);
    float4 acc  = make_float4(0.f, 0.f, 0.f, 0.f);
    int head = lane >> 3;
    const float* sPf = (const float*)&sP[w][0];
    for (int cb = 0; cb < M; cb += 32) {
        int i = cb + lane;
        float4 p = make_float4(0.f, 0.f, 0.f, 0.f);
        int s = 0;
        if (i < M) {
            s = (i == 0) ? d : g_csr[r0 + i - 1];
            float4 a = *(const float4*)&g_asrc[s*4];
            p.x = __expf(lrelu02(a.x + adst.x));
            p.y = __expf(lrelu02(a.y + adst.y));
            p.z = __expf(lrelu02(a.z + adst.z));
            p.w = __expf(lrelu02(a.w + adst.w));
            dsum.x += p.x; dsum.y += p.y; dsum.z += p.z; dsum.w += p.w;
        }
        sSrc[w][lane] = s; sP[w][lane] = p;
        __syncwarp();
        int cnt = M - cb; if (cnt > 32) cnt = 32;
        int j = 0;
        for (; j + 4 <= cnt; j += 4) {
            int s0 = sSrc[w][j],   s1 = sSrc[w][j+1];
            int s2 = sSrc[w][j+2], s3 = sSrc[w][j+3];
            float pk0 = sPf[(j  )*4 + head];
            float pk1 = sPf[(j+1)*4 + head];
            float pk2 = sPf[(j+2)*4 + head];
            float pk3 = sPf[(j+3)*4 + head];
            uint2 h0 = *(const uint2*)&g_hh[s0*HC + 4*lane];
            uint2 h1 = *(const uint2*)&g_hh[s1*HC + 4*lane];
            uint2 h2 = *(const uint2*)&g_hh[s2*HC + 4*lane];
            uint2 h3 = *(const uint2*)&g_hh[s3*HC + 4*lane];
            float2 a0 = __half22float2(*reinterpret_cast<__half2*>(&h0.x));
            float2 b0 = __half22float2(*reinterpret_cast<__half2*>(&h0.y));
            float2 a1 = __half22float2(*reinterpret_cast<__half2*>(&h1.x));
            float2 b1 = __half22float2(*reinterpret_cast<__half2*>(&h1.y));
            float2 a2 = __half22float2(*reinterpret_cast<__half2*>(&h2.x));
            float2 b2 = __half22float2(*reinterpret_cast<__half2*>(&h2.y));
            float2 a3 = __half22float2(*reinterpret_cast<__half2*>(&h3.x));
            float2 b3 = __half22float2(*reinterpret_cast<__half2*>(&h3.y));
            acc.x += pk0*a0.x + pk1*a1.x + pk2*a2.x + pk3*a3.x;
            acc.y += pk0*a0.y + pk1*a1.y + pk2*a2.y + pk3*a3.y;
            acc.z += pk0*b0.x + pk1*b1.x + pk2*b2.x + pk3*b3.x;
            acc.w += pk0*b0.y + pk1*b1.y + pk2*b2.y + pk3*b3.y;
        }
        for (; j < cnt; j++) {
            int sj = sSrc[w][j];
            float pk = sPf[j*4 + head];
            uint2 hv = *(const uint2*)&g_hh[sj*HC + 4*lane];
            float2 f01 = __half22float2(*reinterpret_cast<__half2*>(&hv.x));
            float2 f23 = __half22float2(*reinterpret_cast<__half2*>(&hv.y));
            acc.x += pk*f01.x; acc.y += pk*f01.y;
            acc.z += pk*f23.x; acc.w += pk*f23.y;
        }
        __syncwarp();
    }
#pragma unroll
    for (int off = 16; off > 0; off >>= 1) {
        dsum.x += __shfl_xor_sync(0xffffffffu, dsum.x, off);
        dsum.y += __shfl_xor_sync(0xffffffffu, dsum.y, off);
        dsum.z += __shfl_xor_sync(0xffffffffu, dsum.z, off);
        dsum.w += __shfl_xor_sync(0xffffffffu, dsum.w, off);
    }
    float den = ((head == 0) ? dsum.x : (head == 1) ? dsum.y : (head == 2) ? dsum.z : dsum.w) + 1e-16f;
    float inv = 1.f/den;
    float4 bv = *(const float4*)&bias[4*lane];
    float4 o;
    o.x = fmaxf(acc.x*inv + bv.x, 0.f);
    o.y = fmaxf(acc.y*inv + bv.y, 0.f);
    o.z = fmaxf(acc.z*inv + bv.z, 0.f);
    o.w = fmaxf(acc.w*inv + bv.w, 0.f);
    if (isLast) {
        float* pp = &g_pooled[batch[d]*HC + 4*lane];
        atomicAdd(pp+0, o.x); atomicAdd(pp+1, o.y);
        atomicAdd(pp+2, o.z); atomicAdd(pp+3, o.w);
    } else {
        union { uint2 u; __half2 h[2]; } oo;
        oo.h[0] = __floats2half2_rn(o.x, o.y);
        oo.h[1] = __floats2half2_rn(o.z, o.w);
        *(uint2*)&g_outh[d*HC + 4*lane] = oo.u;
    }
}

// ---------------- conv path tails ----------------
__global__ void k_cb2(const float* __restrict__ cb, const float* __restrict__ Wx) {
    int j = threadIdx.x;
    int r0 = blockIdx.x*128;
    float local = 0.f;
    for (int r = r0; r < r0+128 && r < XTF; r++)
        local += cb[r/LOUTD]*Wx[r*HC + j];
    atomicAdd(&g_cb2[j], local);
}

__global__ void k_applyB(const int* __restrict__ tgt) {
    int g = blockIdx.x, ch = blockIdx.y, j = threadIdx.x;
    float acc = 0.f;
    int t0 = ch*125;
#pragma unroll 5
    for (int tau = t0; tau < t0+125; tau++) {
        int v = __ldg(&tgt[g*LL + tau]);
        acc += __half2float(g_Bh[(v*LL + tau)*HC + j]);
    }
    atomicAdd(&g_xtpre[g*HC + j], acc);
}

__global__ void k_xtfin(const float* __restrict__ xb) {
    int g = blockIdx.x, j = threadIdx.x;
    float v = g_xtpre[g*HC + j] + xb[j] + g_cb2[j];
    g_xc[g*256 + 128 + j] = v > 0.f ? v : 0.f;
}

// ---------------- small dense layers ----------------
__global__ void __launch_bounds__(128) k_fc2(int Asel, int lda,
                     const float* __restrict__ W, const float* __restrict__ b,
                     int Csel, int ldc, int K, int Nout, int doRelu) {
    __shared__ float sA[8*1024];
    const float* A = (Asel == 0) ? g_pooled : (Asel == 1) ? g_xc : g_h1;
    float* C = (Csel == 0) ? g_xc : (Csel == 1) ? g_h1 : g_h2;
    int g0 = blockIdx.x*8;
    for (int i = threadIdx.x; i < 8*K; i += 128) {
        int g8 = i / K, k = i - g8*K;
        sA[g8*K + k] = A[(g0+g8)*lda + k];
    }
    __syncthreads();
    int n = blockIdx.y*128 + threadIdx.x;
    if (n >= Nout) return;
    float acc[8];
#pragma unroll
    for (int g8 = 0; g8 < 8; g8++) acc[g8] = 0.f;
#pragma unroll 2
    for (int k = 0; k < K; k++) {
        float w = W[k*Nout + n];
#pragma unroll
        for (int g8 = 0; g8 < 8; g8++) acc[g8] += sA[g8*K + k]*w;
    }
    float bv = b[n];
#pragma unroll
    for (int g8 = 0; g8 < 8; g8++) {
        float v = acc[g8] + bv;
        if (doRelu && v < 0.f) v = 0.f;
        C[(g0+g8)*ldc + n] = v;
    }
}

__global__ void k_out(const float* __restrict__ ow, const float* __restrict__ ob,
                      float* __restrict__ outp) {
    int g = blockIdx.x, lane = threadIdx.x;
    float s = 0.f;
    for (int k = lane; k < 256; k += 32) s += g_h2[g*256 + k]*ow[k];
#pragma unroll
    for (int off = 16; off > 0; off >>= 1) s += __shfl_xor_sync(0xffffffffu, s, off);
    if (lane == 0) outp[g] = s + ob[0];
}

// ---------------- host (single stream) ----------------
extern "C" void kernel_launch(void* const* d_in, const int* in_sizes, int n_in,
                              void* d_out, int out_size) {
    (void)in_sizes; (void)n_in; (void)out_size;
    const float* x       = (const float*)d_in[0];
    const int*   ei      = (const int*)  d_in[1];
    const int*   batch   = (const int*)  d_in[2];
    const int*   target  = (const int*)  d_in[3];
    const float* W1      = (const float*)d_in[4];
    const float* as1     = (const float*)d_in[5];
    const float* ad1     = (const float*)d_in[6];
    const float* b1      = (const float*)d_in[7];
    const float* Ws      = (const float*)d_in[8];
    const float* ass     = (const float*)d_in[9];
    const float* ads     = (const float*)d_in[10];
    const float* bs      = (const float*)d_in[11];
    const float* fcxd_w  = (const float*)d_in[12];
    const float* fcxd_b  = (const float*)d_in[13];
    const float* emb     = (const float*)d_in[14];
    const float* conv_w  = (const float*)d_in[15];
    const float* conv_b  = (const float*)d_in[16];
    const float* fcxt_w  = (const float*)d_in[17];
    const float* fcxt_b  = (const float*)d_in[18];
    const float* fc1_w   = (const float*)d_in[19];
    const float* fc1_b   = (const float*)d_in[20];
    const float* fc2_w   = (const float*)d_in[21];
    const float* fc2_b   = (const float*)d_in[22];
    const float* out_w   = (const float*)d_in[23];
    const float* out_b   = (const float*)d_in[24];
    const int* esrc = ei;
    const int* edst = ei + EE;

    k_hist<<<(EE+255)/256, 256>>>(edst);                               // 0
    k_scan<<<1, 1024>>>();                                             // 1
    k_prep<<<VOC + (XH_ELEMS + 5*WH_PER_LAYER + WXH2_ELEMS + 255)/256, 256>>>(
        x, W1, Ws, emb, conv_w, fcxt_w);                               // 2
    k_bbuild5<<<LL, 256>>>();                                          // 3 (profiled)
    k_scat_transform<<<SCAT_BLOCKS + NNP/128, 256>>>(esrc, edst, as1, ad1); // 4
    k_aggregate<<<(NN+7)/8, 256>>>(b1, 0, batch);                      // 5

    // conv path tails
    k_cb2<<<(XTF+127)/128, 128>>>(conv_b, fcxt_w);
    k_applyB<<<dim3(GG,8), 128>>>(target);
    k_xtfin<<<GG, 128>>>(fcxt_b);

    // GAT layers 2..5
    for (int l = 0; l < 4; l++) {
        k_transform5<<<NNP/128, 256>>>(l + 1, ass + l*HH*CC, ads + l*HH*CC);
        k_aggregate<<<(NN+7)/8, 256>>>(bs + l*HC, l == 3, batch);
    }

    // xd (writes g_xc[:, :128])
    k_fc2<<<dim3(GG/8,1), 128>>>(0, HC, fcxd_w, fcxd_b, 0, 256, HC, HC, 1);

    // MLP head
    k_fc2<<<dim3(GG/8,8), 128>>>(1, 256,  fc1_w, fc1_b, 1, 1024, 256,  1024, 1);
    k_fc2<<<dim3(GG/8,2), 128>>>(2, 1024, fc2_w, fc2_b, 2, 256,  1024, 256,  1);
    k_out<<<GG, 32>>>(out_w, out_b, (float*)d_out);
}

// round 17
// speedup vs baseline: 1.1359x; 1.0046x over previous
#include <cuda_runtime.h>
#include <cuda_bf16.h>
#include <cuda_fp16.h>
#include <math.h>

#define NN 50000
#define NNP 50048
#define EE 800000
#define GG 256
#define LL 1000
#define HH 4
#define CC 32
#define FDIM 78
#define EDIM 128
#define VOC 26
#define KK 8
#define LOUTD 993
#define HC 128
#define XTF (CC*LOUTD)
#define SCAT_BLOCKS ((EE+255)/256)
#define TB64 (NNP/64)
#define XSTR 96
#define WH_PER_LAYER (4*128*32)
#define XH_ELEMS (NNP*XSTR)
#define WXH2_ELEMS (LOUTD*32*128)

typedef unsigned long long ull;
typedef unsigned int uint32;

__device__ __forceinline__ void mma16816(float* c, const uint32* a, uint32 b0, uint32 b1) {
    asm volatile("mma.sync.aligned.m16n8k16.row.col.f32.f16.f16.f32 "
        "{%0,%1,%2,%3}, {%4,%5,%6,%7}, {%8,%9}, {%0,%1,%2,%3};"
        : "+f"(c[0]), "+f"(c[1]), "+f"(c[2]), "+f"(c[3])
        : "r"(a[0]), "r"(a[1]), "r"(a[2]), "r"(a[3]), "r"(b0), "r"(b1));
}
__device__ __forceinline__ void ldsm4t(uint32* d, uint32 addr) {
    asm volatile("ldmatrix.sync.aligned.m8n8.x4.trans.shared.b16 {%0,%1,%2,%3}, [%4];"
        : "=r"(d[0]), "=r"(d[1]), "=r"(d[2]), "=r"(d[3]) : "r"(addr));
}
__device__ __forceinline__ void cpasync16(uint32 smem_dst, const void* gsrc) {
    asm volatile("cp.async.cg.shared.global [%0], [%1], 16;\n"
                 :: "r"(smem_dst), "l"(gsrc) : "memory");
}
__device__ __forceinline__ void cpcommit() {
    asm volatile("cp.async.commit_group;\n" ::: "memory");
}
template <int N>
__device__ __forceinline__ void cpwait() {
    asm volatile("cp.async.wait_group %0;\n" :: "n"(N) : "memory");
}

// ---------------- scratch ----------------
__device__ __align__(128) __half g_hh[NN*HC];
__device__ __align__(128) __half g_outh[NNP*HC];
__device__ __align__(128) __half g_xh[XH_ELEMS];
__device__ __align__(128) __half g_Wh[5*WH_PER_LAYER];
__device__ __align__(128) __half g_Wxh2[WXH2_ELEMS];   // [t][o][j] fp16 fcxt_w
__device__ __align__(16)  float g_asrc[NN*4];
__device__ __align__(16)  float g_adst[NN*4];
__device__ int   g_rowptr[NN+1];
__device__ int   g_hcnt[NN];
__device__ int   g_cursor[NN];
__device__ int   g_csr[EE];
__device__ __align__(128) __half g_Bh[VOC*LL*HC];
__device__ float g_wsum[VOC*KK*CC];
__device__ float g_cb2[HC];
__device__ __align__(16) float g_pooled[GG*HC];
__device__ float g_xtpre[GG*HC];
__device__ float g_xc[GG*256];
__device__ float g_h1[GG*1024];
__device__ float g_h2[GG*256];

// ---------------- prep: wsum | x->fp16 | W->fp16 | Wx->fp16 [t][o][j] ------
__global__ void k_prep(const float* __restrict__ x, const float* __restrict__ W1,
                       const float* __restrict__ Ws,
                       const float* __restrict__ emb, const float* __restrict__ cw,
                       const float* __restrict__ Wx) {
    if (blockIdx.x < VOC) {
        int v = blockIdx.x, t = threadIdx.x;
        if (t >= CC*KK) return;
        int o = t >> 3, k = t & 7;
        float acc = 0.f;
        for (int i = 0; i < EDIM; i++) acc += emb[v*EDIM + i]*cw[(o*EDIM + i)*KK + k];
        g_wsum[(v*KK + k)*CC + o] = acc;
        return;
    }
    int idx = (blockIdx.x - VOC)*256 + threadIdx.x;
    if (idx < XH_ELEMS) {
        int n = idx / XSTR, f = idx - n*XSTR;
        float v = (n < NN && f < FDIM) ? x[n*FDIM + f] : 0.f;
        g_xh[idx] = __float2half_rn(v);
        return;
    }
    int j = idx - XH_ELEMS;
    if (j < 5*WH_PER_LAYER) {
        int l  = j / WH_PER_LAYER;
        int r  = j - l*WH_PER_LAYER;
        int ch = r >> 12;
        int r2 = r & 4095;
        int col = r2 >> 5;
        int kk  = r2 & 31;
        int f = ch*32 + kk;
        int Fin = (l == 0) ? FDIM : HC;
        const float* Wp = (l == 0) ? W1 : (Ws + (l-1)*HC*HC);
        float v = (f < Fin) ? Wp[f*HC + col] : 0.f;
        g_Wh[j] = __float2half_rn(v);
        return;
    }
    int m = j - 5*WH_PER_LAYER;
    if (m < WXH2_ELEMS) {
        int t = m >> 12;
        int r = m & 4095;
        int o = r >> 7, jj = r & 127;
        g_Wxh2[m] = __float2half_rn(Wx[(o*LOUTD + t)*HC + jj]);
    }
}

// ---------------- CSR build ----------------
__global__ void k_hist(const int* __restrict__ dst) {
    int i = blockIdx.x*256 + threadIdx.x;
    if (i < EE) atomicAdd(&g_hcnt[dst[i]], 1);
}

__global__ void k_scan() {
    __shared__ int sS[1024];
    int t = threadIdx.x;
    const int CH = 49;
    int b0 = t*CH;
    int sum = 0;
    for (int i = 0; i < CH; i++) { int idx = b0+i; if (idx < NN) sum += g_hcnt[idx]; }
    sS[t] = sum; __syncthreads();
    for (int off = 1; off < 1024; off <<= 1) {
        int v = (t >= off) ? sS[t-off] : 0;
        __syncthreads();
        sS[t] += v;
        __syncthreads();
    }
    int run = sS[t] - sum;
    for (int i = 0; i < CH; i++) {
        int idx = b0+i;
        if (idx < NN) {
            int dg = g_hcnt[idx];
            g_rowptr[idx] = run;
            g_cursor[idx] = run;
            g_hcnt[idx] = 0;
            run += dg;
        }
    }
    if (t == 1023) g_rowptr[NN] = sS[1023];
}

// ---------------- bbuild v5: tensor-core MMA ----------------
__global__ void __launch_bounds__(256) k_bbuild5() {
    __shared__ __half wsh[KK*32*40];
    __shared__ __half S_s[2][32*136];
    int tau = blockIdx.x;
    int tid = threadIdx.x;
    int warp = tid >> 5, lane = tid & 31;
    int lr = lane >> 2, hk = lane & 3;
    int quad = lane >> 3, qr = lane & 7;

    for (int i = tid; i < KK*32*40; i += 256) wsh[i] = __float2half_rn(0.f);
    __syncthreads();
    for (int i = tid; i < VOC*KK*CC; i += 256) {
        int v = i >> 8;
        int rem = i & 255;
        int k = rem >> 5, o = rem & 31;
        wsh[k*1280 + v*40 + o] = __float2half_rn(g_wsum[i]);
    }

    int t0 = tau - (KK-1); if (t0 < 0) t0 = 0;
    int t1 = tau;          if (t1 > LOUTD-1) t1 = LOUTD-1;

    uint32 sS0 = (uint32)__cvta_generic_to_shared(&S_s[0][0]);
    const char* WB = (const char*)g_Wxh2;

    {
        int g0 = tid, g1 = tid + 256;
        cpasync16(sS0 + (g0 >> 4)*272 + (g0 & 15)*16,
                  WB + (size_t)t0*8192 + (g0 >> 4)*256 + (g0 & 15)*16);
        cpasync16(sS0 + (g1 >> 4)*272 + (g1 & 15)*16,
                  WB + (size_t)t0*8192 + (g1 >> 4)*256 + (g1 & 15)*16);
        cpcommit();
    }
    __syncthreads();

    float c[4][4];
#pragma unroll
    for (int nt = 0; nt < 4; nt++)
#pragma unroll
        for (int q = 0; q < 4; q++) c[nt][q] = 0.f;

    for (int t = t0; t <= t1; t++) {
        int buf = (t - t0) & 1;
        if (t < t1) {
            int nb = buf ^ 1;
            int g0 = tid, g1 = tid + 256;
            cpasync16(sS0 + nb*8704 + (g0 >> 4)*272 + (g0 & 15)*16,
                      WB + (size_t)(t+1)*8192 + (g0 >> 4)*256 + (g0 & 15)*16);
            cpasync16(sS0 + nb*8704 + (g1 >> 4)*272 + (g1 & 15)*16,
                      WB + (size_t)(t+1)*8192 + (g1 >> 4)*256 + (g1 & 15)*16);
            cpcommit();
            cpwait<1>();
        } else {
            cpwait<0>();
        }
        __syncthreads();
        int k = tau - t;
        uint32 Sb = sS0 + buf*8704;
        const __half* wk = &wsh[k*1280];
#pragma unroll
        for (int kk = 0; kk < 32; kk += 16) {
            uint32 a[4];
            int rowk = kk + ((quad & 2) ? 8 : 0) + qr;
            int colj = warp*16 + ((quad & 1) ? 8 : 0);
            ldsm4t(a, Sb + rowk*272 + colj*2);
#pragma unroll
            for (int nt = 0; nt < 4; nt++) {
                uint32 b0 = *(const uint32*)&wk[(nt*8 + lr)*40 + kk + 2*hk];
                uint32 b1 = *(const uint32*)&wk[(nt*8 + lr)*40 + kk + 2*hk + 8];
                mma16816(c[nt], a, b0, b1);
            }
        }
        __syncthreads();
    }

    int j0 = warp*16 + lr;
#pragma unroll
    for (int nt = 0; nt < 4; nt++) {
        int v0 = nt*8 + 2*hk, v1 = v0 + 1;
        if (v0 < VOC) {
            g_Bh[((size_t)v0*LL + tau)*HC + j0]     = __float2half_rn(c[nt][0]);
            g_Bh[((size_t)v0*LL + tau)*HC + j0 + 8] = __float2half_rn(c[nt][2]);
        }
        if (v1 < VOC) {
            g_Bh[((size_t)v1*LL + tau)*HC + j0]     = __float2half_rn(c[nt][1]);
            g_Bh[((size_t)v1*LL + tau)*HC + j0 + 8] = __float2half_rn(c[nt][3]);
        }
    }
}

// ---------------- transform body v6: 64x128 tile, 3 CTAs/SM target ----------
__device__ __forceinline__ void transform_body6(
        int n0, const __half* __restrict__ act, int strideHalfs, int nCh,
        const __half* __restrict__ Wh,
        const float* __restrict__ asv, const float* __restrict__ adv) {
    __shared__ __half A_s[2][64*40];
    __shared__ __half B_s[2][128*40];
    __shared__ float sAs[256], sAd[256];
    __shared__ float sAv[128], sDv[128];
    int tid = threadIdx.x;
    int warp = tid >> 5, lane = tid & 31;
    int wr = warp & 3, wc = warp >> 2;    // 4 row groups x 2 col groups
    int lr = lane >> 2, hk = lane & 3;

    uint32 sA0 = (uint32)__cvta_generic_to_shared(&A_s[0][0]);
    uint32 sB0 = (uint32)__cvta_generic_to_shared(&B_s[0][0]);
    const int ABUF = 64*40*2;
    const int BBUF = 128*40*2;
    size_t strideB = (size_t)strideHalfs*2;
    const char* actB = (const char*)(act) + (size_t)n0*strideB;
    const char* WhB  = (const char*)Wh;

    if (tid < 256) { sAs[tid] = 0.f; sAd[tid] = 0.f; }
    if (tid < 128) { sAv[tid] = asv[tid]; sDv[tid] = adv[tid]; }

    int gAi = tid >> 2, gAg = tid & 3;                 // 256 A granules
    int gB0i = tid >> 2, gB0g = tid & 3;               // B granules set 0
    int gB1i = (tid + 256) >> 2, gB1g = (tid + 256) & 3;

    {
        cpasync16(sA0 + gAi*80 + gAg*16, actB + (size_t)gAi*strideB + gAg*16);
        cpasync16(sB0 + gB0i*80 + gB0g*16, WhB + gB0i*64 + gB0g*16);
        cpasync16(sB0 + gB1i*80 + gB1g*16, WhB + gB1i*64 + gB1g*16);
        cpcommit();
    }

    float c[8][4];
#pragma unroll
    for (int ni = 0; ni < 8; ni++)
#pragma unroll
        for (int q = 0; q < 4; q++) c[ni][q] = 0.f;

    for (int ci = 0; ci < nCh; ci++) {
        int buf = ci & 1;
        if (ci + 1 < nCh) {
            int nb = buf ^ 1;
            const char* aSrc = actB + (size_t)(ci+1)*64;
            const char* bSrc = WhB + (size_t)(ci+1)*8192;
            cpasync16(sA0 + nb*ABUF + gAi*80 + gAg*16, aSrc + (size_t)gAi*strideB + gAg*16);
            cpasync16(sB0 + nb*BBUF + gB0i*80 + gB0g*16, bSrc + gB0i*64 + gB0g*16);
            cpasync16(sB0 + nb*BBUF + gB1i*80 + gB1g*16, bSrc + gB1i*64 + gB1g*16);
            cpcommit();
            cpwait<1>();
        } else {
            cpwait<0>();
        }
        __syncthreads();
        const __half* As = A_s[buf];
        const __half* Bs = B_s[buf];
#pragma unroll
        for (int kk = 0; kk < 32; kk += 16) {
            uint32 a[4];
            int r = wr*16 + lr;
            int base = r*40 + kk + 2*hk;
            a[0] = *(const uint32*)&As[base];
            a[1] = *(const uint32*)&As[base + 8*40];
            a[2] = *(const uint32*)&As[base + 8];
            a[3] = *(const uint32*)&As[base + 8*40 + 8];
#pragma unroll
            for (int ni = 0; ni < 8; ni++) {
                int cb = wc*64 + ni*8 + lr;
                int bbase = cb*40 + kk + 2*hk;
                uint32 b0 = *(const uint32*)&Bs[bbase];
                uint32 b1 = *(const uint32*)&Bs[bbase + 8];
                mma16816(c[ni], a, b0, b1);
            }
        }
        __syncthreads();
    }

    int lc2 = 2*hk;
    int r0l = wr*16 + lr;
    int r1l = r0l + 8;
    float ps[2][2] = {{0.f,0.f},{0.f,0.f}};
    float pd[2][2] = {{0.f,0.f},{0.f,0.f}};
#pragma unroll
    for (int ni = 0; ni < 8; ni++) {
        int colb = wc*64 + ni*8 + lc2;
        int hl = ni >> 2;
        float av0 = sAv[colb], av1 = sAv[colb+1];
        float dv0 = sDv[colb], dv1 = sDv[colb+1];
        float c0 = c[ni][0], c1 = c[ni][1];
        float c2v = c[ni][2], c3v = c[ni][3];
        ps[0][hl] += c0*av0 + c1*av1;  pd[0][hl] += c0*dv0 + c1*dv1;
        ps[1][hl] += c2v*av0 + c3v*av1; pd[1][hl] += c2v*dv0 + c3v*dv1;
        int n0g = n0 + r0l, n1g = n0 + r1l;
        if (n0g < NN) *(__half2*)&g_hh[n0g*HC + colb] = __floats2half2_rn(c0, c1);
        if (n1g < NN) *(__half2*)&g_hh[n1g*HC + colb] = __floats2half2_rn(c2v, c3v);
    }
    int hb = wc*2;
    atomicAdd(&sAs[r0l*4 + hb + 0], ps[0][0]);
    atomicAdd(&sAs[r0l*4 + hb + 1], ps[0][1]);
    atomicAdd(&sAs[r1l*4 + hb + 0], ps[1][0]);
    atomicAdd(&sAs[r1l*4 + hb + 1], ps[1][1]);
    atomicAdd(&sAd[r0l*4 + hb + 0], pd[0][0]);
    atomicAdd(&sAd[r0l*4 + hb + 1], pd[0][1]);
    atomicAdd(&sAd[r1l*4 + hb + 0], pd[1][0]);
    atomicAdd(&sAd[r1l*4 + hb + 1], pd[1][1]);
    __syncthreads();
    if (tid < 256) {
        int n = n0 + (tid >> 2);
        if (n < NN) {
            g_asrc[n*4 + (tid & 3)] = sAs[tid];
            g_adst[n*4 + (tid & 3)] = sAd[tid];
        }
    }
}

__global__ void __launch_bounds__(256) k_transform6(
        int layer, const float* __restrict__ asv, const float* __restrict__ adv) {
    transform_body6(blockIdx.x*64, g_outh, HC, 4,
                    g_Wh + layer*WH_PER_LAYER, asv, adv);
}

__global__ void __launch_bounds__(256) k_scat_transform(
        const int* __restrict__ src, const int* __restrict__ dst,
        const float* __restrict__ asv, const float* __restrict__ adv) {
    if (blockIdx.x < SCAT_BLOCKS) {
        int i = blockIdx.x*256 + threadIdx.x;
        if (i < EE) {
            int p = atomicAdd(&g_cursor[dst[i]], 1);
            g_csr[p] = src[i];
        }
        if (i < GG*HC) { g_pooled[i] = 0.f; g_xtpre[i] = 0.f; }
        if (i < HC) g_cb2[i] = 0.f;
        return;
    }
    transform_body6((blockIdx.x - SCAT_BLOCKS)*64, g_xh, XSTR, 3, g_Wh, asv, adv);
}

__device__ __forceinline__ float lrelu02(float v) { return v > 0.f ? v : 0.2f*v; }

// ---------------- single-pass softmax + aggregate (fp16 gather) -------------
__global__ void k_aggregate(const float* __restrict__ bias, int isLast,
                            const int* __restrict__ batch) {
    __shared__ int    sSrc[8][32];
    __shared__ float4 sP[8][32];
    int w = threadIdx.x >> 5, lane = threadIdx.x & 31;
    int d = blockIdx.x*8 + w;
    if (d >= NN) return;
    int r0 = g_rowptr[d], r1 = g_rowptr[d+1];
    int M = r1 - r0 + 1;
    float4 adst = *(const float4*)&g_adst[d*4];

    float4 dsum = make_float4(0.f, 0.f, 0.f, 0.f);
    float4 acc  = make_float4(0.f, 0.f, 0.f, 0.f);
    int head = lane >> 3;
    const float* sPf = (const float*)&sP[w][0];
    for (int cb = 0; cb < M; cb += 32) {
        int i = cb + lane;
        float4 p = make_float4(0.f, 0.f, 0.f, 0.f);
        int s = 0;
        if (i < M) {
            s = (i == 0) ? d : g_csr[r0 + i - 1];
            float4 a = *(const float4*)&g_asrc[s*4];
            p.x = __expf(lrelu02(a.x + adst.x));
            p.y = __expf(lrelu02(a.y + adst.y));
            p.z = __expf(lrelu02(a.z + adst.z));
            p.w = __expf(lrelu02(a.w + adst.w));
            dsum.x += p.x; dsum.y += p.y; dsum.z += p.z; dsum.w += p.w;
        }
        sSrc[w][lane] = s; sP[w][lane] = p;
        __syncwarp();
        int cnt = M - cb; if (cnt > 32) cnt = 32;
        int j = 0;
        for (; j + 4 <= cnt; j += 4) {
            int s0 = sSrc[w][j],   s1 = sSrc[w][j+1];
            int s2 = sSrc[w][j+2], s3 = sSrc[w][j+3];
            float pk0 = sPf[(j  )*4 + head];
            float pk1 = sPf[(j+1)*4 + head];
            float pk2 = sPf[(j+2)*4 + head];
            float pk3 = sPf[(j+3)*4 + head];
            uint2 h0 = *(const uint2*)&g_hh[s0*HC + 4*lane];
            uint2 h1 = *(const uint2*)&g_hh[s1*HC + 4*lane];
            uint2 h2 = *(const uint2*)&g_hh[s2*HC + 4*lane];
            uint2 h3 = *(const uint2*)&g_hh[s3*HC + 4*lane];
            float2 a0 = __half22float2(*reinterpret_cast<__half2*>(&h0.x));
            float2 b0 = __half22float2(*reinterpret_cast<__half2*>(&h0.y));
            float2 a1 = __half22float2(*reinterpret_cast<__half2*>(&h1.x));
            float2 b1 = __half22float2(*reinterpret_cast<__half2*>(&h1.y));
            float2 a2 = __half22float2(*reinterpret_cast<__half2*>(&h2.x));
            float2 b2 = __half22float2(*reinterpret_cast<__half2*>(&h2.y));
            float2 a3 = __half22float2(*reinterpret_cast<__half2*>(&h3.x));
            float2 b3 = __half22float2(*reinterpret_cast<__half2*>(&h3.y));
            acc.x += pk0*a0.x + pk1*a1.x + pk2*a2.x + pk3*a3.x;
            acc.y += pk0*a0.y + pk1*a1.y + pk2*a2.y + pk3*a3.y;
            acc.z += pk0*b0.x + pk1*b1.x + pk2*b2.x + pk3*b3.x;
            acc.w += pk0*b0.y + pk1*b1.y + pk2*b2.y + pk3*b3.y;
        }
        for (; j < cnt; j++) {
            int sj = sSrc[w][j];
            float pk = sPf[j*4 + head];
            uint2 hv = *(const uint2*)&g_hh[sj*HC + 4*lane];
            float2 f01 = __half22float2(*reinterpret_cast<__half2*>(&hv.x));
            float2 f23 = __half22float2(*reinterpret_cast<__half2*>(&hv.y));
            acc.x += pk*f01.x; acc.y += pk*f01.y;
            acc.z += pk*f23.x; acc.w += pk*f23.y;
        }
        __syncwarp();
    }
#pragma unroll
    for (int off = 16; off > 0; off >>= 1) {
        dsum.x += __shfl_xor_sync(0xffffffffu, dsum.x, off);
        dsum.y += __shfl_xor_sync(0xffffffffu, dsum.y, off);
        dsum.z += __shfl_xor_sync(0xffffffffu, dsum.z, off);
        dsum.w += __shfl_xor_sync(0xffffffffu, dsum.w, off);
    }
    float den = ((head == 0) ? dsum.x : (head == 1) ? dsum.y : (head == 2) ? dsum.z : dsum.w) + 1e-16f;
    float inv = 1.f/den;
    float4 bv = *(const float4*)&bias[4*lane];
    float4 o;
    o.x = fmaxf(acc.x*inv + bv.x, 0.f);
    o.y = fmaxf(acc.y*inv + bv.y, 0.f);
    o.z = fmaxf(acc.z*inv + bv.z, 0.f);
    o.w = fmaxf(acc.w*inv + bv.w, 0.f);
    if (isLast) {
        float* pp = &g_pooled[batch[d]*HC + 4*lane];
        atomicAdd(pp+0, o.x); atomicAdd(pp+1, o.y);
        atomicAdd(pp+2, o.z); atomicAdd(pp+3, o.w);
    } else {
        union { uint2 u; __half2 h[2]; } oo;
        oo.h[0] = __floats2half2_rn(o.x, o.y);
        oo.h[1] = __floats2half2_rn(o.z, o.w);
        *(uint2*)&g_outh[d*HC + 4*lane] = oo.u;
    }
}

// ---------------- conv path tails ----------------
// cb2 from fp16 Wxh2 [t][o][j]; block handles 8 t values
__global__ void k_cb2(const float* __restrict__ cb) {
    int j = threadIdx.x;
    int tb = blockIdx.x*8;
    float local = 0.f;
    for (int t = tb; t < tb+8 && t < LOUTD; t++)
        for (int o = 0; o < CC; o++)
            local += cb[o]*__half2float(g_Wxh2[(size_t)t*4096 + o*128 + j]);
    atomicAdd(&g_cb2[j], local);
}

__global__ void k_applyB(const int* __restrict__ tgt) {
    int g = blockIdx.x, ch = blockIdx.y, j = threadIdx.x;
    float acc = 0.f;
    int t0 = ch*125;
#pragma unroll 5
    for (int tau = t0; tau < t0+125; tau++) {
        int v = __ldg(&tgt[g*LL + tau]);
        acc += __half2float(g_Bh[(v*LL + tau)*HC + j]);
    }
    atomicAdd(&g_xtpre[g*HC + j], acc);
}

__global__ void k_xtfin(const float* __restrict__ xb) {
    int g = blockIdx.x, j = threadIdx.x;
    float v = g_xtpre[g*HC + j] + xb[j] + g_cb2[j];
    g_xc[g*256 + 128 + j] = v > 0.f ? v : 0.f;
}

// ---------------- small dense layers ----------------
__global__ void __launch_bounds__(128) k_fc2(int Asel, int lda,
                     const float* __restrict__ W, const float* __restrict__ b,
                     int Csel, int ldc, int K, int Nout, int doRelu) {
    __shared__ float sA[8*1024];
    const float* A = (Asel == 0) ? g_pooled : (Asel == 1) ? g_xc : g_h1;
    float* C = (Csel == 0) ? g_xc : (Csel == 1) ? g_h1 : g_h2;
    int g0 = blockIdx.x*8;
    for (int i = threadIdx.x; i < 8*K; i += 128) {
        int g8 = i / K, k = i - g8*K;
        sA[g8*K + k] = A[(g0+g8)*lda + k];
    }
    __syncthreads();
    int n = blockIdx.y*128 + threadIdx.x;
    if (n >= Nout) return;
    float acc[8];
#pragma unroll
    for (int g8 = 0; g8 < 8; g8++) acc[g8] = 0.f;
#pragma unroll 2
    for (int k = 0; k < K; k++) {
        float w = W[k*Nout + n];
#pragma unroll
        for (int g8 = 0; g8 < 8; g8++) acc[g8] += sA[g8*K + k]*w;
    }
    float bv = b[n];
#pragma unroll
    for (int g8 = 0; g8 < 8; g8++) {
        float v = acc[g8] + bv;
        if (doRelu && v < 0.f) v = 0.f;
        C[(g0+g8)*ldc + n] = v;
    }
}

__global__ void k_out(const float* __restrict__ ow, const float* __restrict__ ob,
                      float* __restrict__ outp) {
    int g = blockIdx.x, lane = threadIdx.x;
    float s = 0.f;
    for (int k = lane; k < 256; k += 32) s += g_h2[g*256 + k]*ow[k];
#pragma unroll
    for (int off = 16; off > 0; off >>= 1) s += __shfl_xor_sync(0xffffffffu, s, off);
    if (lane == 0) outp[g] = s + ob[0];
}

// ---------------- host (single stream) ----------------
extern "C" void kernel_launch(void* const* d_in, const int* in_sizes, int n_in,
                              void* d_out, int out_size) {
    (void)in_sizes; (void)n_in; (void)out_size;
    const float* x       = (const float*)d_in[0];
    const int*   ei      = (const int*)  d_in[1];
    const int*   batch   = (const int*)  d_in[2];
    const int*   target  = (const int*)  d_in[3];
    const float* W1      = (const float*)d_in[4];
    const float* as1     = (const float*)d_in[5];
    const float* ad1     = (const float*)d_in[6];
    const float* b1      = (const float*)d_in[7];
    const float* Ws      = (const float*)d_in[8];
    const float* ass     = (const float*)d_in[9];
    const float* ads     = (const float*)d_in[10];
    const float* bs      = (const float*)d_in[11];
    const float* fcxd_w  = (const float*)d_in[12];
    const float* fcxd_b  = (const float*)d_in[13];
    const float* emb     = (const float*)d_in[14];
    const float* conv_w  = (const float*)d_in[15];
    const float* conv_b  = (const float*)d_in[16];
    const float* fcxt_w  = (const float*)d_in[17];
    const float* fcxt_b  = (const float*)d_in[18];
    const float* fc1_w   = (const float*)d_in[19];
    const float* fc1_b   = (const float*)d_in[20];
    const float* fc2_w   = (const float*)d_in[21];
    const float* fc2_b   = (const float*)d_in[22];
    const float* out_w   = (const float*)d_in[23];
    const float* out_b   = (const float*)d_in[24];
    const int* esrc = ei;
    const int* edst = ei + EE;

    k_hist<<<(EE+255)/256, 256>>>(edst);                               // 0
    k_scan<<<1, 1024>>>();                                             // 1
    k_prep<<<VOC + (XH_ELEMS + 5*WH_PER_LAYER + WXH2_ELEMS + 255)/256, 256>>>(
        x, W1, Ws, emb, conv_w, fcxt_w);                               // 2
    k_scat_transform<<<SCAT_BLOCKS + TB64, 256>>>(esrc, edst, as1, ad1); // 3 (profiled)
    k_bbuild5<<<LL, 256>>>();                                          // 4
    k_aggregate<<<(NN+7)/8, 256>>>(b1, 0, batch);                      // 5

    // conv path tails
    k_cb2<<<(LOUTD+7)/8, 128>>>(conv_b);
    k_applyB<<<dim3(GG,8), 128>>>(target);
    k_xtfin<<<GG, 128>>>(fcxt_b);

    // GAT layers 2..5
    for (int l = 0; l < 4; l++) {
        k_transform6<<<TB64, 256>>>(l + 1, ass + l*HH*CC, ads + l*HH*CC);
        k_aggregate<<<(NN+7)/8, 256>>>(bs + l*HC, l == 3, batch);
    }

    // xd (writes g_xc[:, :128])
    k_fc2<<<dim3(GG/8,1), 128>>>(0, HC, fcxd_w, fcxd_b, 0, 256, HC, HC, 1);

    // MLP head
    k_fc2<<<dim3(GG/8,8), 128>>>(1, 256,  fc1_w, fc1_b, 1, 1024, 256,  1024, 1);
    k_fc2<<<dim3(GG/8,2), 128>>>(2, 1024, fc2_w, fc2_b, 2, 256,  1024, 256,  1);
    k_out<<<GG, 32>>>(out_w, out_b, (float*)d_out);
}